// round 16
// baseline (speedup 1.0000x reference)
#include <cuda_runtime.h>
#include <math.h>

#define D_MODEL 768
#define NTOK 1043
#define NPAT 1024
#define NCLS 19
#define BATCH 8
#define NHEADS 12
#define DHEAD 64
#define ROWS (BATCH*NTOK)      /* 8344 */
#define DFF 3072
#define GSZ 32
#define IMG 512

// ---------------- scratch (static device globals; no allocation) ----------------
__device__ float g_X [ROWS*D_MODEL];
__device__ float g_H [ROWS*D_MODEL];
__device__ float g_Q [BATCH*NHEADS*NTOK*DHEAD];
__device__ float g_Kb[BATCH*NHEADS*NTOK*DHEAD];
__device__ float g_Vb[BATCH*NHEADS*NTOK*DHEAD];
__device__ float g_M [ROWS*DFF];
__device__ float g_Pp[BATCH*NPAT*D_MODEL];
__device__ float g_Pc[BATCH*NCLS*D_MODEL];
__device__ float g_invp[BATCH*NPAT];
__device__ float g_invc[BATCH*NCLS];
__device__ float g_msk[BATCH*NCLS*GSZ*GSZ];

// ---------------- tf32 helpers ----------------
__device__ __forceinline__ unsigned f2tf32(float f) {
    unsigned u;
    asm("cvt.rna.tf32.f32 %0, %1;" : "=r"(u) : "f"(f));
    return u;
}
__device__ __forceinline__ void mma_tf32(float* d, const unsigned* a, const unsigned* b) {
    asm volatile(
        "mma.sync.aligned.m16n8k8.row.col.f32.tf32.tf32.f32 "
        "{%0,%1,%2,%3}, {%4,%5,%6,%7}, {%8,%9}, {%0,%1,%2,%3};"
        : "+f"(d[0]), "+f"(d[1]), "+f"(d[2]), "+f"(d[3])
        : "r"(a[0]), "r"(a[1]), "r"(a[2]), "r"(a[3]), "r"(b[0]), "r"(b[1]));
}

// ---------------- tf32 tensor-core GEMM (R4 single-buffered version) ----------
// 128x128 tile, BK=16, 256 threads (8 warps, each 64Mx32N = 4x4 m16n8k8 tiles).
// Row remap: logical row r of A maps to global row (r/rpb)*bstr + r%rpb + roff.
// Same remap form (crpb,cbstr,croff) applied to C (and residual R).
// EPI: 0 = bias only, 1 = bias+GELU(exact), 2 = bias + residual add (R).
template<int EPI>
__global__ __launch_bounds__(256) void tgemm_k(
    const float* __restrict__ A, const float* __restrict__ W,
    const float* __restrict__ bias, float* __restrict__ C,
    const float* __restrict__ R,
    int M, int N, int K,
    int rpb, int bstr, int roff,
    int crpb, int cbstr, int croff)
{
    __shared__ unsigned As[16][136];   // [k][m], stride 136 -> conflict-free frags
    __shared__ unsigned Bs[16][136];   // [k][n]
    const int t    = threadIdx.x;
    const int lane = t & 31, w = t >> 5;
    const int wm   = (w >> 2) * 64;    // warp M offset (0 or 64)
    const int wn   = (w & 3) * 32;     // warp N offset (0,32,64,96)
    const int r    = lane >> 2, c = lane & 3;
    const int m0   = blockIdx.y * 128, n0 = blockIdx.x * 128;

    // A loader: thread -> row (t>>1), k-half (t&1)*8
    const int alr  = t >> 1;
    const int akq  = (t & 1) * 8;
    const int arow = m0 + alr;
    const bool av  = (arow < M);
    int aidx = 0;
    if (av) aidx = ((arow / rpb) * bstr + arow % rpb + roff) * K + akq;
    // B loader: thread -> k row (t>>4), col (t&15)*8
    const int blr = t >> 4;
    const int bcl = (t & 15) * 8;

    float acc[4][4][4];
#pragma unroll
    for (int i = 0; i < 4; i++)
#pragma unroll
        for (int j = 0; j < 4; j++)
#pragma unroll
            for (int q = 0; q < 4; q++) acc[i][j][q] = 0.f;

    for (int k0 = 0; k0 < K; k0 += 16) {
        float4 a4a = make_float4(0.f,0.f,0.f,0.f), a4b = a4a;
        if (av) {
            a4a = *(const float4*)(A + aidx + k0);
            a4b = *(const float4*)(A + aidx + k0 + 4);
        }
        As[akq+0][alr] = f2tf32(a4a.x); As[akq+1][alr] = f2tf32(a4a.y);
        As[akq+2][alr] = f2tf32(a4a.z); As[akq+3][alr] = f2tf32(a4a.w);
        As[akq+4][alr] = f2tf32(a4b.x); As[akq+5][alr] = f2tf32(a4b.y);
        As[akq+6][alr] = f2tf32(a4b.z); As[akq+7][alr] = f2tf32(a4b.w);
        {
            const float* bp = W + (k0 + blr) * N + n0 + bcl;
            float4 b4a = *(const float4*)(bp);
            float4 b4b = *(const float4*)(bp + 4);
            Bs[blr][bcl+0] = f2tf32(b4a.x); Bs[blr][bcl+1] = f2tf32(b4a.y);
            Bs[blr][bcl+2] = f2tf32(b4a.z); Bs[blr][bcl+3] = f2tf32(b4a.w);
            Bs[blr][bcl+4] = f2tf32(b4b.x); Bs[blr][bcl+5] = f2tf32(b4b.y);
            Bs[blr][bcl+6] = f2tf32(b4b.z); Bs[blr][bcl+7] = f2tf32(b4b.w);
        }
        __syncthreads();
#pragma unroll
        for (int ks = 0; ks < 2; ks++) {
            const int kb = ks * 8;
            unsigned af[4][4], bf[4][2];
#pragma unroll
            for (int mt = 0; mt < 4; mt++) {
                int m = wm + mt*16 + r;
                af[mt][0] = As[kb+c  ][m];
                af[mt][1] = As[kb+c  ][m+8];
                af[mt][2] = As[kb+c+4][m];
                af[mt][3] = As[kb+c+4][m+8];
            }
#pragma unroll
            for (int nt = 0; nt < 4; nt++) {
                int n = wn + nt*8 + r;
                bf[nt][0] = Bs[kb+c  ][n];
                bf[nt][1] = Bs[kb+c+4][n];
            }
#pragma unroll
            for (int mt = 0; mt < 4; mt++)
#pragma unroll
                for (int nt = 0; nt < 4; nt++)
                    mma_tf32(acc[mt][nt], af[mt], bf[nt]);
        }
        __syncthreads();
    }

    // epilogue: acc layout c0:(r,2c) c1:(r,2c+1) c2:(r+8,2c) c3:(r+8,2c+1)
#pragma unroll
    for (int mt = 0; mt < 4; mt++) {
#pragma unroll
        for (int half = 0; half < 2; half++) {
            int grow = m0 + wm + mt*16 + r + half*8;
            if (grow >= M) continue;
            int cg = ((grow / crpb) * cbstr + grow % crpb + croff) * N;
#pragma unroll
            for (int nt = 0; nt < 4; nt++) {
                int ncol = n0 + wn + nt*8 + c*2;
                float v0 = acc[mt][nt][half*2+0];
                float v1 = acc[mt][nt][half*2+1];
                if (bias) { v0 += bias[ncol]; v1 += bias[ncol+1]; }
                if (EPI == 1) {
                    v0 = 0.5f * v0 * (1.f + erff(v0 * 0.70710678118f));
                    v1 = 0.5f * v1 * (1.f + erff(v1 * 0.70710678118f));
                }
                if (EPI == 2) { v0 += R[cg + ncol]; v1 += R[cg + ncol + 1]; }
                C[cg + ncol]     = v0;
                C[cg + ncol + 1] = v1;
            }
        }
    }
}

// ---------------- LayerNorm over D_MODEL ----------------
__global__ __launch_bounds__(256) void ln_k(const float* __restrict__ In,
                                            float* __restrict__ Out,
                                            const float* __restrict__ g,
                                            const float* __restrict__ b)
{
    __shared__ float rs[256], rs2[256];
    const int row = blockIdx.x;
    const int t = threadIdx.x;
    const float* x = In + row * D_MODEL;
    float v[3]; float s = 0.f, s2 = 0.f;
#pragma unroll
    for (int i = 0; i < 3; i++) {
        v[i] = x[t + i*256]; s += v[i]; s2 += v[i]*v[i];
    }
    rs[t] = s; rs2[t] = s2; __syncthreads();
    for (int off = 128; off > 0; off >>= 1) {
        if (t < off) { rs[t] += rs[t+off]; rs2[t] += rs2[t+off]; }
        __syncthreads();
    }
    float mean = rs[0] * (1.f/768.f);
    float var  = rs2[0] * (1.f/768.f) - mean*mean;
    float inv  = rsqrtf(var + 1e-5f);
#pragma unroll
    for (int i = 0; i < 3; i++) {
        int c = t + i*256;
        Out[row * D_MODEL + c] = (v[i] - mean) * inv * g[c] + b[c];
    }
}

// ---------------- cls-token concat ----------------
__global__ void clsfill_k(const float* __restrict__ cls, float* __restrict__ X)
{
    int idx = blockIdx.x * 256 + threadIdx.x;
    if (idx >= BATCH*NCLS*D_MODEL) return;
    int d = idx % D_MODEL;
    int c = (idx / D_MODEL) % NCLS;
    int b = idx / (D_MODEL*NCLS);
    X[(b*NTOK + NPAT + c)*D_MODEL + d] = cls[c*D_MODEL + d];
}

// ---------------- per-head QKV projection (64x64 per head) ----------------
__global__ __launch_bounds__(256) void qkv_k(
    const float* __restrict__ H,
    const float* __restrict__ qW, const float* __restrict__ qb,
    const float* __restrict__ kW, const float* __restrict__ kb,
    const float* __restrict__ vW, const float* __restrict__ vb,
    float* __restrict__ Q, float* __restrict__ Ko, float* __restrict__ Vo, int l)
{
    __shared__ float At[64][68];
    __shared__ float Wt[64][68];
    const int t = threadIdx.x, tx = t & 15, ty = t >> 4;
    const int bh = blockIdx.y, b = bh / NHEADS, h = bh % NHEADS;
    const int s0 = blockIdx.x * 64;

    {
        int r = t >> 2, c0 = (t & 3) * 16;
        int srow = s0 + r;
        const float* ar = H + (b*NTOK + srow)*D_MODEL + h*64;
#pragma unroll
        for (int i = 0; i < 4; i++) {
            float4 av = (srow < NTOK) ? *(const float4*)(ar + c0 + i*4)
                                      : make_float4(0.f,0.f,0.f,0.f);
            *(float4*)&At[r][c0 + i*4] = av;
        }
    }
    const int woff = (l*NHEADS + h) * 64 * 64;
    const int boff = (l*NHEADS + h) * 64;
    const float* Wp[3] = {qW + woff, kW + woff, vW + woff};
    const float* Bp[3] = {qb + boff, kb + boff, vb + boff};
    float* Op[3] = {Q, Ko, Vo};

    for (int w = 0; w < 3; w++) {
        __syncthreads();
        {
            int r = t >> 2, c0 = (t & 3) * 16;
#pragma unroll
            for (int i = 0; i < 4; i++)
                *(float4*)&Wt[r][c0 + i*4] = *(const float4*)(Wp[w] + r*64 + c0 + i*4);
        }
        __syncthreads();
        float acc[4][4];
#pragma unroll
        for (int i = 0; i < 4; i++)
#pragma unroll
            for (int j = 0; j < 4; j++) acc[i][j] = 0.f;
#pragma unroll
        for (int d = 0; d < 64; d++) {
            float a0 = At[ty*4+0][d], a1 = At[ty*4+1][d];
            float a2 = At[ty*4+2][d], a3 = At[ty*4+3][d];
            float4 wv = *(float4*)&Wt[d][tx*4];
            acc[0][0]+=a0*wv.x; acc[0][1]+=a0*wv.y; acc[0][2]+=a0*wv.z; acc[0][3]+=a0*wv.w;
            acc[1][0]+=a1*wv.x; acc[1][1]+=a1*wv.y; acc[1][2]+=a1*wv.z; acc[1][3]+=a1*wv.w;
            acc[2][0]+=a2*wv.x; acc[2][1]+=a2*wv.y; acc[2][2]+=a2*wv.z; acc[2][3]+=a2*wv.w;
            acc[3][0]+=a3*wv.x; acc[3][1]+=a3*wv.y; acc[3][2]+=a3*wv.z; acc[3][3]+=a3*wv.w;
        }
        float scale = (w == 0) ? 0.125f : 1.f;
#pragma unroll
        for (int i = 0; i < 4; i++) {
            int ss = s0 + ty*4 + i;
            if (ss < NTOK) {
                float* o = Op[w] + (bh*NTOK + ss)*64 + tx*4;
#pragma unroll
                for (int j = 0; j < 4; j++)
                    o[j] = (acc[i][j] + Bp[w][tx*4 + j]) * scale;
            }
        }
    }
}

// ---------------- flash attention (fp32), 32 q-rows x 64-key chunks -----------
// 256 threads = 16 tx (4 keys each) x 16 ty (2 rows each).
// P buffer aliases kt (fully consumed before overwrite). Residual-adds into X.
__global__ __launch_bounds__(256) void attn_k(
    const float* __restrict__ Q, const float* __restrict__ K,
    const float* __restrict__ V, float* __restrict__ X)
{
    __shared__ float qs[32][68];
    __shared__ float kt[64][68];   // [d][key]; rows 0..31 reused as P[row][key]
    __shared__ float vs[64][68];   // [key][d]
    float (*ps)[68] = kt;

    const int t = threadIdx.x, tx = t & 15, ty = t >> 4;
    const int bh = blockIdx.y, b = bh / NHEADS, h = bh % NHEADS;
    const int s0 = blockIdx.x * 32;
    const int r0 = ty * 2, r1 = r0 + 1;

    {   // load Q tile: thread -> row t>>3, cols (t&7)*8..+7
        int r = t >> 3, c0 = (t & 7) * 8;
        int s = s0 + r;
        const float* qr = Q + (bh*NTOK + s)*64 + c0;
        float4 qa = make_float4(0.f,0.f,0.f,0.f), qb4 = qa;
        if (s < NTOK) { qa = *(const float4*)(qr); qb4 = *(const float4*)(qr + 4); }
        *(float4*)&qs[r][c0]     = qa;
        *(float4*)&qs[r][c0 + 4] = qb4;
    }

    float m_i[2] = {-1e30f, -1e30f}, l_i[2] = {0.f, 0.f};
    float o[2][4];
#pragma unroll
    for (int i = 0; i < 2; i++)
#pragma unroll
        for (int j = 0; j < 4; j++) o[i][j] = 0.f;

    const int nkt = (NTOK + 63) / 64;   // 17
    for (int kti = 0; kti < nkt; kti++) {
        const int kbase = kti * 64;
        {   // load K (transposed) + V: thread -> key t>>2, cols (t&3)*16..+15
            int kk = t >> 2, c0 = (t & 3) * 16;
            int gk = kbase + kk;
            bool ok = (gk < NTOK);
            const float* kr = K + (bh*NTOK + gk)*64 + c0;
            const float* vr = V + (bh*NTOK + gk)*64 + c0;
#pragma unroll
            for (int i = 0; i < 4; i++) {
                float4 k4 = ok ? *(const float4*)(kr + i*4) : make_float4(0.f,0.f,0.f,0.f);
                kt[c0+i*4+0][kk] = k4.x; kt[c0+i*4+1][kk] = k4.y;
                kt[c0+i*4+2][kk] = k4.z; kt[c0+i*4+3][kk] = k4.w;
                float4 v4 = ok ? *(const float4*)(vr + i*4) : make_float4(0.f,0.f,0.f,0.f);
                *(float4*)&vs[kk][c0 + i*4] = v4;
            }
        }
        __syncthreads();

        // S = Q @ K^T  (2 rows x 4 keys per thread)
        float sr[2][4];
#pragma unroll
        for (int i = 0; i < 2; i++)
#pragma unroll
            for (int j = 0; j < 4; j++) sr[i][j] = 0.f;
#pragma unroll 8
        for (int d = 0; d < 64; d++) {
            float q0 = qs[r0][d], q1 = qs[r1][d];
            float4 kv = *(float4*)&kt[d][tx*4];
            sr[0][0] += q0*kv.x; sr[0][1] += q0*kv.y; sr[0][2] += q0*kv.z; sr[0][3] += q0*kv.w;
            sr[1][0] += q1*kv.x; sr[1][1] += q1*kv.y; sr[1][2] += q1*kv.z; sr[1][3] += q1*kv.w;
        }
#pragma unroll
        for (int j = 0; j < 4; j++) {
            if (kbase + tx*4 + j >= NTOK) { sr[0][j] = -1e30f; sr[1][j] = -1e30f; }
        }
        // online softmax (row spans 16 lanes; xor 1,2,4,8 stays in half-warp)
        float p[2][4];
#pragma unroll
        for (int i = 0; i < 2; i++) {
            float mx = fmaxf(fmaxf(sr[i][0], sr[i][1]), fmaxf(sr[i][2], sr[i][3]));
#pragma unroll
            for (int off = 1; off < 16; off <<= 1)
                mx = fmaxf(mx, __shfl_xor_sync(0xffffffffu, mx, off));
            float mnew = fmaxf(m_i[i], mx);
            float psum = 0.f;
#pragma unroll
            for (int j = 0; j < 4; j++) { p[i][j] = __expf(sr[i][j] - mnew); psum += p[i][j]; }
#pragma unroll
            for (int off = 1; off < 16; off <<= 1)
                psum += __shfl_xor_sync(0xffffffffu, psum, off);
            float alpha = __expf(m_i[i] - mnew);
            l_i[i] = l_i[i] * alpha + psum;
            m_i[i] = mnew;
            o[i][0] *= alpha; o[i][1] *= alpha; o[i][2] *= alpha; o[i][3] *= alpha;
        }
        __syncthreads();   // all kt reads done before P overwrites it
#pragma unroll
        for (int j = 0; j < 4; j++) { ps[r0][tx*4+j] = p[0][j]; ps[r1][tx*4+j] = p[1][j]; }
        __syncthreads();

        // O += P @ V
#pragma unroll 8
        for (int k = 0; k < 64; k++) {
            float4 vv = *(float4*)&vs[k][tx*4];
            float p0 = ps[r0][k], p1 = ps[r1][k];
            o[0][0] += p0*vv.x; o[0][1] += p0*vv.y; o[0][2] += p0*vv.z; o[0][3] += p0*vv.w;
            o[1][0] += p1*vv.x; o[1][1] += p1*vv.y; o[1][2] += p1*vv.z; o[1][3] += p1*vv.w;
        }
        __syncthreads();   // before next chunk overwrites kt/vs
    }
#pragma unroll
    for (int i = 0; i < 2; i++) {
        int s = s0 + r0 + i;
        if (s < NTOK) {
            float inv = 1.f / l_i[i];
            float* xp = X + (b*NTOK + s)*D_MODEL + h*64 + tx*4;
#pragma unroll
            for (int j = 0; j < 4; j++) xp[j] += o[i][j] * inv;
        }
    }
}

// ---------------- row inverse L2 norm ----------------
__global__ __launch_bounds__(256) void invnorm_k(const float* __restrict__ P,
                                                 float* __restrict__ inv)
{
    __shared__ float rs[256];
    const int row = blockIdx.x, t = threadIdx.x;
    const float* x = P + row * D_MODEL;
    float s = 0.f;
#pragma unroll
    for (int i = 0; i < 3; i++) { float v = x[t + i*256]; s += v*v; }
    rs[t] = s; __syncthreads();
    for (int off = 128; off > 0; off >>= 1) {
        if (t < off) rs[t] += rs[t+off];
        __syncthreads();
    }
    if (t == 0) inv[row] = rsqrtf(rs[0]);
}

// ---------------- cosine masks + mask-LN over 19 classes ----------------
__global__ __launch_bounds__(608) void masks_k(
    const float* __restrict__ Pp, const float* __restrict__ Pc,
    const float* __restrict__ invp, const float* __restrict__ invc,
    const float* __restrict__ mg, const float* __restrict__ mb,
    float* __restrict__ msk)
{
    __shared__ float vals[NCLS];
    const int row = blockIdx.x;
    const int b = row >> 10, n = row & 1023;
    const int w = threadIdx.x >> 5, lane = threadIdx.x & 31;
    const float* p = Pp + row * D_MODEL;
    const float* c = Pc + (b*NCLS + w) * D_MODEL;
    float s = 0.f;
    for (int i = lane; i < D_MODEL; i += 32) s += p[i] * c[i];
#pragma unroll
    for (int off = 16; off > 0; off >>= 1)
        s += __shfl_xor_sync(0xffffffffu, s, off);
    if (lane == 0) vals[w] = s * invp[row] * invc[b*NCLS + w];
    __syncthreads();
    float mean = 0.f;
#pragma unroll
    for (int i = 0; i < NCLS; i++) mean += vals[i];
    mean *= (1.f/NCLS);
    float var = 0.f;
#pragma unroll
    for (int i = 0; i < NCLS; i++) { float d = vals[i]-mean; var += d*d; }
    var *= (1.f/NCLS);
    float inv = rsqrtf(var + 1e-5f);
    if (lane == 0)
        msk[(b*NCLS + w)*1024 + n] = (vals[w]-mean)*inv*mg[w] + mb[w];
}

// ---------------- bilinear resize 32x32 -> 512x512 ----------------
__global__ void resize_k(const float* __restrict__ msk, float* __restrict__ out)
{
    int idx = blockIdx.x * 256 + threadIdx.x;
    if (idx >= BATCH*NCLS*IMG*IMG) return;
    int x = idx & 511;
    int y = (idx >> 9) & 511;
    int bc = idx >> 18;
    float sx = (x + 0.5f) * 0.0625f - 0.5f;
    float sy = (y + 0.5f) * 0.0625f - 0.5f;
    float fx0 = floorf(sx), fy0 = floorf(sy);
    float fx = sx - fx0, fy = sy - fy0;
    int x0 = min(31, max(0, (int)fx0));
    int x1 = min(31, max(0, (int)fx0 + 1));
    int y0 = min(31, max(0, (int)fy0));
    int y1 = min(31, max(0, (int)fy0 + 1));
    const float* m = msk + bc * 1024;
    float v00 = m[y0*32 + x0], v01 = m[y0*32 + x1];
    float v10 = m[y1*32 + x0], v11 = m[y1*32 + x1];
    out[idx] = (v00*(1.f-fx) + v01*fx)*(1.f-fy) + (v10*(1.f-fx) + v11*fx)*fy;
}

// ---------------- host launch ----------------
extern "C" void kernel_launch(void* const* d_in, const int* in_sizes, int n_in,
                              void* d_out, int out_size)
{
    const float* x          = (const float*)d_in[0];
    const float* proj_dec_W = (const float*)d_in[1];
    const float* proj_dec_b = (const float*)d_in[2];
    const float* cls_emb    = (const float*)d_in[3];
    const float* ln1_g      = (const float*)d_in[4];
    const float* ln1_b      = (const float*)d_in[5];
    const float* qW         = (const float*)d_in[6];
    const float* qb         = (const float*)d_in[7];
    const float* kW         = (const float*)d_in[8];
    const float* kb         = (const float*)d_in[9];
    const float* vW         = (const float*)d_in[10];
    const float* vb         = (const float*)d_in[11];
    const float* ln2_g      = (const float*)d_in[12];
    const float* ln2_b      = (const float*)d_in[13];
    const float* mlp_W1     = (const float*)d_in[14];
    const float* mlp_b1     = (const float*)d_in[15];
    const float* mlp_W2     = (const float*)d_in[16];
    const float* mlp_b2     = (const float*)d_in[17];
    const float* proj_patch = (const float*)d_in[18];
    const float* proj_cls   = (const float*)d_in[19];
    const float* dec_g      = (const float*)d_in[20];
    const float* dec_b      = (const float*)d_in[21];
    const float* mask_g     = (const float*)d_in[22];
    const float* mask_b     = (const float*)d_in[23];
    (void)in_sizes; (void)n_in; (void)out_size;

    float *X, *H, *Q, *Kb, *Vb, *M, *Pp, *Pc, *invp, *invc, *msk;
    cudaGetSymbolAddress((void**)&X,    g_X);
    cudaGetSymbolAddress((void**)&H,    g_H);
    cudaGetSymbolAddress((void**)&Q,    g_Q);
    cudaGetSymbolAddress((void**)&Kb,   g_Kb);
    cudaGetSymbolAddress((void**)&Vb,   g_Vb);
    cudaGetSymbolAddress((void**)&M,    g_M);
    cudaGetSymbolAddress((void**)&Pp,   g_Pp);
    cudaGetSymbolAddress((void**)&Pc,   g_Pc);
    cudaGetSymbolAddress((void**)&invp, g_invp);
    cudaGetSymbolAddress((void**)&invc, g_invc);
    cudaGetSymbolAddress((void**)&msk,  g_msk);

    const dim3 blk(256);
    const int MP = BATCH * NPAT;  // 8192

    tgemm_k<0><<<dim3(6, 64), blk>>>(x, proj_dec_W, proj_dec_b, X, nullptr,
                                     MP, D_MODEL, D_MODEL,
                                     MP, 0, 0, NPAT, NTOK, 0);
    clsfill_k<<<(BATCH*NCLS*D_MODEL + 255)/256, blk>>>(cls_emb, X);

    for (int l = 0; l < 2; l++) {
        ln_k<<<ROWS, blk>>>(X, H, ln1_g + l*D_MODEL, ln1_b + l*D_MODEL);
        qkv_k<<<dim3(17, BATCH*NHEADS), blk>>>(H, qW, qb, kW, kb, vW, vb,
                                               Q, Kb, Vb, l);
        attn_k<<<dim3(33, BATCH*NHEADS), blk>>>(Q, Kb, Vb, X);
        ln_k<<<ROWS, blk>>>(X, H, ln2_g + l*D_MODEL, ln2_b + l*D_MODEL);
        tgemm_k<1><<<dim3(24, 66), blk>>>(H, mlp_W1 + l*D_MODEL*DFF,
                                          mlp_b1 + l*DFF, M, nullptr,
                                          ROWS, DFF, D_MODEL,
                                          ROWS, 0, 0, ROWS, 0, 0);
        tgemm_k<2><<<dim3(6, 66), blk>>>(M, mlp_W2 + l*DFF*D_MODEL,
                                         mlp_b2 + l*D_MODEL, X, X,
                                         ROWS, D_MODEL, DFF,
                                         ROWS, 0, 0, ROWS, 0, 0);
    }

    ln_k<<<ROWS, blk>>>(X, H, dec_g, dec_b);
    tgemm_k<0><<<dim3(6, 64), blk>>>(H, proj_patch, nullptr, Pp, nullptr,
                                     MP, D_MODEL, D_MODEL,
                                     NPAT, NTOK, 0, MP, 0, 0);
    tgemm_k<0><<<dim3(6, 2), blk>>>(H, proj_cls, nullptr, Pc, nullptr,
                                    BATCH*NCLS, D_MODEL, D_MODEL,
                                    NCLS, NTOK, NPAT, BATCH*NCLS, 0, 0);
    invnorm_k<<<MP, blk>>>(Pp, invp);
    invnorm_k<<<BATCH*NCLS, blk>>>(Pc, invc);
    masks_k<<<MP, 608>>>(Pp, Pc, invp, invc, mask_g, mask_b, msk);
    resize_k<<<(BATCH*NCLS*IMG*IMG + 255)/256, blk>>>(msk, (float*)d_out);
}

// round 17
// speedup vs baseline: 1.2316x; 1.2316x over previous
#include <cuda_runtime.h>
#include <math.h>

#define D_MODEL 768
#define NTOK 1043
#define NPAT 1024
#define NCLS 19
#define BATCH 8
#define NHEADS 12
#define DHEAD 64
#define ROWS (BATCH*NTOK)      /* 8344 */
#define DFF 3072
#define GSZ 32
#define IMG 512

// ---------------- scratch (static device globals; no allocation) ----------------
__device__ float g_X [ROWS*D_MODEL];
__device__ float g_H [ROWS*D_MODEL];
__device__ float g_Q [BATCH*NHEADS*NTOK*DHEAD];
__device__ float g_Kb[BATCH*NHEADS*NTOK*DHEAD];
__device__ float g_Vb[BATCH*NHEADS*NTOK*DHEAD];
__device__ float g_M [ROWS*DFF];
__device__ float g_Pp[BATCH*NPAT*D_MODEL];
__device__ float g_Pc[BATCH*NCLS*D_MODEL];
__device__ float g_invp[BATCH*NPAT];
__device__ float g_invc[BATCH*NCLS];
__device__ float g_msk[BATCH*NCLS*GSZ*GSZ];

// ---------------- tf32 helpers ----------------
__device__ __forceinline__ unsigned f2tf32(float f) {
    unsigned u;
    asm("cvt.rna.tf32.f32 %0, %1;" : "=r"(u) : "f"(f));
    return u;
}
__device__ __forceinline__ void mma_tf32(float* d, const unsigned* a, const unsigned* b) {
    asm volatile(
        "mma.sync.aligned.m16n8k8.row.col.f32.tf32.tf32.f32 "
        "{%0,%1,%2,%3}, {%4,%5,%6,%7}, {%8,%9}, {%0,%1,%2,%3};"
        : "+f"(d[0]), "+f"(d[1]), "+f"(d[2]), "+f"(d[3])
        : "r"(a[0]), "r"(a[1]), "r"(a[2]), "r"(a[3]), "r"(b[0]), "r"(b[1]));
}

// ---------------- tf32 tensor-core GEMM, double-buffered (measured -199us) ----
// 128x128 tile, BK=16, 256 threads (8 warps, each 64Mx32N = 4x4 m16n8k8 tiles).
// Two-stage smem ping-pong with register prefetch; 1 sync per k-tile.
// Row remap: logical row r of A maps to global row (r/rpb)*bstr + r%rpb + roff.
// Same remap form (crpb,cbstr,croff) applied to C (and residual R).
// EPI: 0 = bias only, 1 = bias+GELU(exact), 2 = bias + residual add (R).
template<int EPI>
__global__ __launch_bounds__(256) void tgemm_k(
    const float* __restrict__ A, const float* __restrict__ W,
    const float* __restrict__ bias, float* __restrict__ C,
    const float* __restrict__ R,
    int M, int N, int K,
    int rpb, int bstr, int roff,
    int crpb, int cbstr, int croff)
{
    __shared__ unsigned As[2][16][136];
    __shared__ unsigned Bs[2][16][136];
    const int t    = threadIdx.x;
    const int lane = t & 31, w = t >> 5;
    const int wm   = (w >> 2) * 64;
    const int wn   = (w & 3) * 32;
    const int r    = lane >> 2, c = lane & 3;
    const int m0   = blockIdx.y * 128, n0 = blockIdx.x * 128;

    const int alr  = t >> 1;
    const int akq  = (t & 1) * 8;
    const int arow = m0 + alr;
    const bool av  = (arow < M);
    int aidx = 0;
    if (av) aidx = ((arow / rpb) * bstr + arow % rpb + roff) * K + akq;
    const int blr = t >> 4;
    const int bcl = (t & 15) * 8;

    float acc[4][4][4];
#pragma unroll
    for (int i = 0; i < 4; i++)
#pragma unroll
        for (int j = 0; j < 4; j++)
#pragma unroll
            for (int q = 0; q < 4; q++) acc[i][j][q] = 0.f;

    const int niter = K >> 4;
    float4 a4a, a4b, b4a, b4b;

    // prologue: load + stage tile 0
    {
        a4a = make_float4(0.f,0.f,0.f,0.f); a4b = a4a;
        if (av) { a4a = *(const float4*)(A + aidx); a4b = *(const float4*)(A + aidx + 4); }
        const float* bp = W + blr * N + n0 + bcl;
        b4a = *(const float4*)(bp); b4b = *(const float4*)(bp + 4);
        As[0][akq+0][alr] = f2tf32(a4a.x); As[0][akq+1][alr] = f2tf32(a4a.y);
        As[0][akq+2][alr] = f2tf32(a4a.z); As[0][akq+3][alr] = f2tf32(a4a.w);
        As[0][akq+4][alr] = f2tf32(a4b.x); As[0][akq+5][alr] = f2tf32(a4b.y);
        As[0][akq+6][alr] = f2tf32(a4b.z); As[0][akq+7][alr] = f2tf32(a4b.w);
        Bs[0][blr][bcl+0] = f2tf32(b4a.x); Bs[0][blr][bcl+1] = f2tf32(b4a.y);
        Bs[0][blr][bcl+2] = f2tf32(b4a.z); Bs[0][blr][bcl+3] = f2tf32(b4a.w);
        Bs[0][blr][bcl+4] = f2tf32(b4b.x); Bs[0][blr][bcl+5] = f2tf32(b4b.y);
        Bs[0][blr][bcl+6] = f2tf32(b4b.z); Bs[0][blr][bcl+7] = f2tf32(b4b.w);
    }
    __syncthreads();

    for (int it = 0; it < niter; it++) {
        if (it + 1 < niter) {
            const int k0 = (it + 1) << 4;
            a4a = make_float4(0.f,0.f,0.f,0.f); a4b = a4a;
            if (av) { a4a = *(const float4*)(A + aidx + k0); a4b = *(const float4*)(A + aidx + k0 + 4); }
            const float* bp = W + (k0 + blr) * N + n0 + bcl;
            b4a = *(const float4*)(bp); b4b = *(const float4*)(bp + 4);
        }
        const int p = it & 1;
#pragma unroll
        for (int ks = 0; ks < 2; ks++) {
            const int kb = ks * 8;
            unsigned af[4][4], bf[4][2];
#pragma unroll
            for (int mt = 0; mt < 4; mt++) {
                int m = wm + mt*16 + r;
                af[mt][0] = As[p][kb+c  ][m];
                af[mt][1] = As[p][kb+c  ][m+8];
                af[mt][2] = As[p][kb+c+4][m];
                af[mt][3] = As[p][kb+c+4][m+8];
            }
#pragma unroll
            for (int nt = 0; nt < 4; nt++) {
                int n = wn + nt*8 + r;
                bf[nt][0] = Bs[p][kb+c  ][n];
                bf[nt][1] = Bs[p][kb+c+4][n];
            }
#pragma unroll
            for (int mt = 0; mt < 4; mt++)
#pragma unroll
                for (int nt = 0; nt < 4; nt++)
                    mma_tf32(acc[mt][nt], af[mt], bf[nt]);
        }
        if (it + 1 < niter) {
            const int q = (it + 1) & 1;
            As[q][akq+0][alr] = f2tf32(a4a.x); As[q][akq+1][alr] = f2tf32(a4a.y);
            As[q][akq+2][alr] = f2tf32(a4a.z); As[q][akq+3][alr] = f2tf32(a4a.w);
            As[q][akq+4][alr] = f2tf32(a4b.x); As[q][akq+5][alr] = f2tf32(a4b.y);
            As[q][akq+6][alr] = f2tf32(a4b.z); As[q][akq+7][alr] = f2tf32(a4b.w);
            Bs[q][blr][bcl+0] = f2tf32(b4a.x); Bs[q][blr][bcl+1] = f2tf32(b4a.y);
            Bs[q][blr][bcl+2] = f2tf32(b4a.z); Bs[q][blr][bcl+3] = f2tf32(b4a.w);
            Bs[q][blr][bcl+4] = f2tf32(b4b.x); Bs[q][blr][bcl+5] = f2tf32(b4b.y);
            Bs[q][blr][bcl+6] = f2tf32(b4b.z); Bs[q][blr][bcl+7] = f2tf32(b4b.w);
            __syncthreads();
        }
    }

    // epilogue: acc layout c0:(r,2c) c1:(r,2c+1) c2:(r+8,2c) c3:(r+8,2c+1)
#pragma unroll
    for (int mt = 0; mt < 4; mt++) {
#pragma unroll
        for (int half = 0; half < 2; half++) {
            int grow = m0 + wm + mt*16 + r + half*8;
            if (grow >= M) continue;
            int cg = ((grow / crpb) * cbstr + grow % crpb + croff) * N;
#pragma unroll
            for (int nt = 0; nt < 4; nt++) {
                int ncol = n0 + wn + nt*8 + c*2;
                float v0 = acc[mt][nt][half*2+0];
                float v1 = acc[mt][nt][half*2+1];
                if (bias) { v0 += bias[ncol]; v1 += bias[ncol+1]; }
                if (EPI == 1) {
                    v0 = 0.5f * v0 * (1.f + erff(v0 * 0.70710678118f));
                    v1 = 0.5f * v1 * (1.f + erff(v1 * 0.70710678118f));
                }
                if (EPI == 2) { v0 += R[cg + ncol]; v1 += R[cg + ncol + 1]; }
                C[cg + ncol]     = v0;
                C[cg + ncol + 1] = v1;
            }
        }
    }
}

// ---------------- LayerNorm over D_MODEL ----------------
__global__ __launch_bounds__(256) void ln_k(const float* __restrict__ In,
                                            float* __restrict__ Out,
                                            const float* __restrict__ g,
                                            const float* __restrict__ b)
{
    __shared__ float rs[256], rs2[256];
    const int row = blockIdx.x;
    const int t = threadIdx.x;
    const float* x = In + row * D_MODEL;
    float v[3]; float s = 0.f, s2 = 0.f;
#pragma unroll
    for (int i = 0; i < 3; i++) {
        v[i] = x[t + i*256]; s += v[i]; s2 += v[i]*v[i];
    }
    rs[t] = s; rs2[t] = s2; __syncthreads();
    for (int off = 128; off > 0; off >>= 1) {
        if (t < off) { rs[t] += rs[t+off]; rs2[t] += rs2[t+off]; }
        __syncthreads();
    }
    float mean = rs[0] * (1.f/768.f);
    float var  = rs2[0] * (1.f/768.f) - mean*mean;
    float inv  = rsqrtf(var + 1e-5f);
#pragma unroll
    for (int i = 0; i < 3; i++) {
        int c = t + i*256;
        Out[row * D_MODEL + c] = (v[i] - mean) * inv * g[c] + b[c];
    }
}

// ---------------- cls-token concat ----------------
__global__ void clsfill_k(const float* __restrict__ cls, float* __restrict__ X)
{
    int idx = blockIdx.x * 256 + threadIdx.x;
    if (idx >= BATCH*NCLS*D_MODEL) return;
    int d = idx % D_MODEL;
    int c = (idx / D_MODEL) % NCLS;
    int b = idx / (D_MODEL*NCLS);
    X[(b*NTOK + NPAT + c)*D_MODEL + d] = cls[c*D_MODEL + d];
}

// ---------------- per-head QKV projection (64x64 per head) ----------------
__global__ __launch_bounds__(256) void qkv_k(
    const float* __restrict__ H,
    const float* __restrict__ qW, const float* __restrict__ qb,
    const float* __restrict__ kW, const float* __restrict__ kb,
    const float* __restrict__ vW, const float* __restrict__ vb,
    float* __restrict__ Q, float* __restrict__ Ko, float* __restrict__ Vo, int l)
{
    __shared__ float At[64][68];
    __shared__ float Wt[64][68];
    const int t = threadIdx.x, tx = t & 15, ty = t >> 4;
    const int bh = blockIdx.y, b = bh / NHEADS, h = bh % NHEADS;
    const int s0 = blockIdx.x * 64;

    {
        int r = t >> 2, c0 = (t & 3) * 16;
        int srow = s0 + r;
        const float* ar = H + (b*NTOK + srow)*D_MODEL + h*64;
#pragma unroll
        for (int i = 0; i < 4; i++) {
            float4 av = (srow < NTOK) ? *(const float4*)(ar + c0 + i*4)
                                      : make_float4(0.f,0.f,0.f,0.f);
            *(float4*)&At[r][c0 + i*4] = av;
        }
    }
    const int woff = (l*NHEADS + h) * 64 * 64;
    const int boff = (l*NHEADS + h) * 64;
    const float* Wp[3] = {qW + woff, kW + woff, vW + woff};
    const float* Bp[3] = {qb + boff, kb + boff, vb + boff};
    float* Op[3] = {Q, Ko, Vo};

    for (int w = 0; w < 3; w++) {
        __syncthreads();
        {
            int r = t >> 2, c0 = (t & 3) * 16;
#pragma unroll
            for (int i = 0; i < 4; i++)
                *(float4*)&Wt[r][c0 + i*4] = *(const float4*)(Wp[w] + r*64 + c0 + i*4);
        }
        __syncthreads();
        float acc[4][4];
#pragma unroll
        for (int i = 0; i < 4; i++)
#pragma unroll
            for (int j = 0; j < 4; j++) acc[i][j] = 0.f;
#pragma unroll
        for (int d = 0; d < 64; d++) {
            float a0 = At[ty*4+0][d], a1 = At[ty*4+1][d];
            float a2 = At[ty*4+2][d], a3 = At[ty*4+3][d];
            float4 wv = *(float4*)&Wt[d][tx*4];
            acc[0][0]+=a0*wv.x; acc[0][1]+=a0*wv.y; acc[0][2]+=a0*wv.z; acc[0][3]+=a0*wv.w;
            acc[1][0]+=a1*wv.x; acc[1][1]+=a1*wv.y; acc[1][2]+=a1*wv.z; acc[1][3]+=a1*wv.w;
            acc[2][0]+=a2*wv.x; acc[2][1]+=a2*wv.y; acc[2][2]+=a2*wv.z; acc[2][3]+=a2*wv.w;
            acc[3][0]+=a3*wv.x; acc[3][1]+=a3*wv.y; acc[3][2]+=a3*wv.z; acc[3][3]+=a3*wv.w;
        }
        float scale = (w == 0) ? 0.125f : 1.f;
#pragma unroll
        for (int i = 0; i < 4; i++) {
            int ss = s0 + ty*4 + i;
            if (ss < NTOK) {
                float* o = Op[w] + (bh*NTOK + ss)*64 + tx*4;
#pragma unroll
                for (int j = 0; j < 4; j++)
                    o[j] = (acc[i][j] + Bp[w][tx*4 + j]) * scale;
            }
        }
    }
}

// ---------------- flash attention (R4 version: 64 q-rows, 32-key chunks) ------
// Writes residual add into X. Measured-good at 4382us config.
__global__ __launch_bounds__(256) void attn_k(
    const float* __restrict__ Q, const float* __restrict__ K,
    const float* __restrict__ V, float* __restrict__ X)
{
    __shared__ float qs[64][68];
    __shared__ float kt[64][36];
    __shared__ float vs[32][68];
    __shared__ float Ps[64][33];
    const int t = threadIdx.x, tx = t & 15, ty = t >> 4;
    const int bh = blockIdx.y, b = bh / NHEADS, h = bh % NHEADS;
    const int s0 = blockIdx.x * 64;

    {
        int r = t >> 2, c0 = (t & 3) * 16;
        int s = s0 + r;
        const float* qr = Q + (bh*NTOK + s)*64;
#pragma unroll
        for (int i = 0; i < 4; i++) {
            float4 qv = (s < NTOK) ? *(const float4*)(qr + c0 + i*4)
                                   : make_float4(0.f,0.f,0.f,0.f);
            *(float4*)&qs[r][c0 + i*4] = qv;
        }
    }
    float m_i[4], l_i[4], o[4][4];
#pragma unroll
    for (int i = 0; i < 4; i++) {
        m_i[i] = -1e30f; l_i[i] = 0.f;
#pragma unroll
        for (int j = 0; j < 4; j++) o[i][j] = 0.f;
    }

    const int nkt = (NTOK + 31) / 32;
    for (int kti = 0; kti < nkt; kti++) {
        const int kbase = kti * 32;
        {
            int r = t >> 3, c0 = (t & 7) * 8;
            int gk = kbase + r;
            const float* kr = K + (bh*NTOK + gk)*64;
            const float* vr = V + (bh*NTOK + gk)*64;
            bool ok = (gk < NTOK);
#pragma unroll
            for (int i = 0; i < 2; i++) {
                float4 k4 = ok ? *(const float4*)(kr + c0 + i*4) : make_float4(0.f,0.f,0.f,0.f);
                kt[c0+i*4+0][r] = k4.x; kt[c0+i*4+1][r] = k4.y;
                kt[c0+i*4+2][r] = k4.z; kt[c0+i*4+3][r] = k4.w;
                float4 v4 = ok ? *(const float4*)(vr + c0 + i*4) : make_float4(0.f,0.f,0.f,0.f);
                *(float4*)&vs[r][c0 + i*4] = v4;
            }
        }
        __syncthreads();

        float sr[4][2];
#pragma unroll
        for (int i = 0; i < 4; i++) { sr[i][0] = 0.f; sr[i][1] = 0.f; }
#pragma unroll
        for (int d = 0; d < 64; d++) {
            float a0 = qs[ty*4+0][d], a1 = qs[ty*4+1][d];
            float a2 = qs[ty*4+2][d], a3 = qs[ty*4+3][d];
            float b0 = kt[d][tx*2+0], b1 = kt[d][tx*2+1];
            sr[0][0]+=a0*b0; sr[0][1]+=a0*b1;
            sr[1][0]+=a1*b0; sr[1][1]+=a1*b1;
            sr[2][0]+=a2*b0; sr[2][1]+=a2*b1;
            sr[3][0]+=a3*b0; sr[3][1]+=a3*b1;
        }
#pragma unroll
        for (int j = 0; j < 2; j++) {
            if (kbase + tx*2 + j >= NTOK) {
#pragma unroll
                for (int i = 0; i < 4; i++) sr[i][j] = -1e30f;
            }
        }
#pragma unroll
        for (int i = 0; i < 4; i++) {
            float mx = fmaxf(sr[i][0], sr[i][1]);
#pragma unroll
            for (int off = 1; off < 16; off <<= 1)
                mx = fmaxf(mx, __shfl_xor_sync(0xffffffffu, mx, off));
            float mnew = fmaxf(m_i[i], mx);
            float p0 = __expf(sr[i][0] - mnew);
            float p1 = __expf(sr[i][1] - mnew);
            float ps = p0 + p1;
#pragma unroll
            for (int off = 1; off < 16; off <<= 1)
                ps += __shfl_xor_sync(0xffffffffu, ps, off);
            float alpha = __expf(m_i[i] - mnew);
            l_i[i] = l_i[i] * alpha + ps;
            m_i[i] = mnew;
            Ps[ty*4+i][tx*2+0] = p0;
            Ps[ty*4+i][tx*2+1] = p1;
            o[i][0] *= alpha; o[i][1] *= alpha; o[i][2] *= alpha; o[i][3] *= alpha;
        }
        __syncthreads();
#pragma unroll 8
        for (int k = 0; k < 32; k++) {
            float4 vv = *(float4*)&vs[k][tx*4];
            float p0 = Ps[ty*4+0][k], p1 = Ps[ty*4+1][k];
            float p2 = Ps[ty*4+2][k], p3 = Ps[ty*4+3][k];
            o[0][0]+=p0*vv.x; o[0][1]+=p0*vv.y; o[0][2]+=p0*vv.z; o[0][3]+=p0*vv.w;
            o[1][0]+=p1*vv.x; o[1][1]+=p1*vv.y; o[1][2]+=p1*vv.z; o[1][3]+=p1*vv.w;
            o[2][0]+=p2*vv.x; o[2][1]+=p2*vv.y; o[2][2]+=p2*vv.z; o[2][3]+=p2*vv.w;
            o[3][0]+=p3*vv.x; o[3][1]+=p3*vv.y; o[3][2]+=p3*vv.z; o[3][3]+=p3*vv.w;
        }
        __syncthreads();
    }
#pragma unroll
    for (int i = 0; i < 4; i++) {
        int s = s0 + ty*4 + i;
        if (s < NTOK) {
            float inv = 1.f / l_i[i];
            float* xp = X + (b*NTOK + s)*D_MODEL + h*64 + tx*4;
#pragma unroll
            for (int j = 0; j < 4; j++) xp[j] += o[i][j] * inv;
        }
    }
}

// ---------------- row inverse L2 norm ----------------
__global__ __launch_bounds__(256) void invnorm_k(const float* __restrict__ P,
                                                 float* __restrict__ inv)
{
    __shared__ float rs[256];
    const int row = blockIdx.x, t = threadIdx.x;
    const float* x = P + row * D_MODEL;
    float s = 0.f;
#pragma unroll
    for (int i = 0; i < 3; i++) { float v = x[t + i*256]; s += v*v; }
    rs[t] = s; __syncthreads();
    for (int off = 128; off > 0; off >>= 1) {
        if (t < off) rs[t] += rs[t+off];
        __syncthreads();
    }
    if (t == 0) inv[row] = rsqrtf(rs[0]);
}

// ---------------- cosine masks + mask-LN over 19 classes ----------------
__global__ __launch_bounds__(608) void masks_k(
    const float* __restrict__ Pp, const float* __restrict__ Pc,
    const float* __restrict__ invp, const float* __restrict__ invc,
    const float* __restrict__ mg, const float* __restrict__ mb,
    float* __restrict__ msk)
{
    __shared__ float vals[NCLS];
    const int row = blockIdx.x;
    const int b = row >> 10, n = row & 1023;
    const int w = threadIdx.x >> 5, lane = threadIdx.x & 31;
    const float* p = Pp + row * D_MODEL;
    const float* c = Pc + (b*NCLS + w) * D_MODEL;
    float s = 0.f;
    for (int i = lane; i < D_MODEL; i += 32) s += p[i] * c[i];
#pragma unroll
    for (int off = 16; off > 0; off >>= 1)
        s += __shfl_xor_sync(0xffffffffu, s, off);
    if (lane == 0) vals[w] = s * invp[row] * invc[b*NCLS + w];
    __syncthreads();
    float mean = 0.f;
#pragma unroll
    for (int i = 0; i < NCLS; i++) mean += vals[i];
    mean *= (1.f/NCLS);
    float var = 0.f;
#pragma unroll
    for (int i = 0; i < NCLS; i++) { float d = vals[i]-mean; var += d*d; }
    var *= (1.f/NCLS);
    float inv = rsqrtf(var + 1e-5f);
    if (lane == 0)
        msk[(b*NCLS + w)*1024 + n] = (vals[w]-mean)*inv*mg[w] + mb[w];
}

// ---------------- bilinear resize 32x32 -> 512x512 ----------------
__global__ void resize_k(const float* __restrict__ msk, float* __restrict__ out)
{
    int idx = blockIdx.x * 256 + threadIdx.x;
    if (idx >= BATCH*NCLS*IMG*IMG) return;
    int x = idx & 511;
    int y = (idx >> 9) & 511;
    int bc = idx >> 18;
    float sx = (x + 0.5f) * 0.0625f - 0.5f;
    float sy = (y + 0.5f) * 0.0625f - 0.5f;
    float fx0 = floorf(sx), fy0 = floorf(sy);
    float fx = sx - fx0, fy = sy - fy0;
    int x0 = min(31, max(0, (int)fx0));
    int x1 = min(31, max(0, (int)fx0 + 1));
    int y0 = min(31, max(0, (int)fy0));
    int y1 = min(31, max(0, (int)fy0 + 1));
    const float* m = msk + bc * 1024;
    float v00 = m[y0*32 + x0], v01 = m[y0*32 + x1];
    float v10 = m[y1*32 + x0], v11 = m[y1*32 + x1];
    out[idx] = (v00*(1.f-fx) + v01*fx)*(1.f-fy) + (v10*(1.f-fx) + v11*fx)*fy;
}

// ---------------- host launch ----------------
extern "C" void kernel_launch(void* const* d_in, const int* in_sizes, int n_in,
                              void* d_out, int out_size)
{
    const float* x          = (const float*)d_in[0];
    const float* proj_dec_W = (const float*)d_in[1];
    const float* proj_dec_b = (const float*)d_in[2];
    const float* cls_emb    = (const float*)d_in[3];
    const float* ln1_g      = (const float*)d_in[4];
    const float* ln1_b      = (const float*)d_in[5];
    const float* qW         = (const float*)d_in[6];
    const float* qb         = (const float*)d_in[7];
    const float* kW         = (const float*)d_in[8];
    const float* kb         = (const float*)d_in[9];
    const float* vW         = (const float*)d_in[10];
    const float* vb         = (const float*)d_in[11];
    const float* ln2_g      = (const float*)d_in[12];
    const float* ln2_b      = (const float*)d_in[13];
    const float* mlp_W1     = (const float*)d_in[14];
    const float* mlp_b1     = (const float*)d_in[15];
    const float* mlp_W2     = (const float*)d_in[16];
    const float* mlp_b2     = (const float*)d_in[17];
    const float* proj_patch = (const float*)d_in[18];
    const float* proj_cls   = (const float*)d_in[19];
    const float* dec_g      = (const float*)d_in[20];
    const float* dec_b      = (const float*)d_in[21];
    const float* mask_g     = (const float*)d_in[22];
    const float* mask_b     = (const float*)d_in[23];
    (void)in_sizes; (void)n_in; (void)out_size;

    float *X, *H, *Q, *Kb, *Vb, *M, *Pp, *Pc, *invp, *invc, *msk;
    cudaGetSymbolAddress((void**)&X,    g_X);
    cudaGetSymbolAddress((void**)&H,    g_H);
    cudaGetSymbolAddress((void**)&Q,    g_Q);
    cudaGetSymbolAddress((void**)&Kb,   g_Kb);
    cudaGetSymbolAddress((void**)&Vb,   g_Vb);
    cudaGetSymbolAddress((void**)&M,    g_M);
    cudaGetSymbolAddress((void**)&Pp,   g_Pp);
    cudaGetSymbolAddress((void**)&Pc,   g_Pc);
    cudaGetSymbolAddress((void**)&invp, g_invp);
    cudaGetSymbolAddress((void**)&invc, g_invc);
    cudaGetSymbolAddress((void**)&msk,  g_msk);

    const dim3 blk(256);
    const int MP = BATCH * NPAT;  // 8192

    tgemm_k<0><<<dim3(6, 64), blk>>>(x, proj_dec_W, proj_dec_b, X, nullptr,
                                     MP, D_MODEL, D_MODEL,
                                     MP, 0, 0, NPAT, NTOK, 0);
    clsfill_k<<<(BATCH*NCLS*D_MODEL + 255)/256, blk>>>(cls_emb, X);

    for (int l = 0; l < 2; l++) {
        ln_k<<<ROWS, blk>>>(X, H, ln1_g + l*D_MODEL, ln1_b + l*D_MODEL);
        qkv_k<<<dim3(17, BATCH*NHEADS), blk>>>(H, qW, qb, kW, kb, vW, vb,
                                               Q, Kb, Vb, l);
        attn_k<<<dim3(17, BATCH*NHEADS), blk>>>(Q, Kb, Vb, X);
        ln_k<<<ROWS, blk>>>(X, H, ln2_g + l*D_MODEL, ln2_b + l*D_MODEL);
        tgemm_k<1><<<dim3(24, 66), blk>>>(H, mlp_W1 + l*D_MODEL*DFF,
                                          mlp_b1 + l*DFF, M, nullptr,
                                          ROWS, DFF, D_MODEL,
                                          ROWS, 0, 0, ROWS, 0, 0);
        tgemm_k<2><<<dim3(6, 66), blk>>>(M, mlp_W2 + l*DFF*D_MODEL,
                                         mlp_b2 + l*D_MODEL, X, X,
                                         ROWS, D_MODEL, DFF,
                                         ROWS, 0, 0, ROWS, 0, 0);
    }

    ln_k<<<ROWS, blk>>>(X, H, dec_g, dec_b);
    tgemm_k<0><<<dim3(6, 64), blk>>>(H, proj_patch, nullptr, Pp, nullptr,
                                     MP, D_MODEL, D_MODEL,
                                     NPAT, NTOK, 0, MP, 0, 0);
    tgemm_k<0><<<dim3(6, 2), blk>>>(H, proj_cls, nullptr, Pc, nullptr,
                                    BATCH*NCLS, D_MODEL, D_MODEL,
                                    NCLS, NTOK, NPAT, BATCH*NCLS, 0, 0);
    invnorm_k<<<MP, blk>>>(Pp, invp);
    invnorm_k<<<BATCH*NCLS, blk>>>(Pc, invc);
    masks_k<<<MP, 608>>>(Pp, Pc, invp, invc, mask_g, mask_b, msk);
    resize_k<<<(BATCH*NCLS*IMG*IMG + 255)/256, blk>>>(msk, (float*)d_out);
}